// round 16
// baseline (speedup 1.0000x reference)
#include <cuda_runtime.h>

// DynamicMaskHead fused kernel, round 16:
//  = round-15 (59.2us) + two slot-count cuts:
//  (1) layer-0 row-term sharing: ryd is identical for pixel-lanes A and B,
//      so fold it into the bias ONCE per channel (saves 8 FFMA2/unit on the
//      binding fma pipe)
//  (2) phase-2 row-pairing: output rows 2p and 2p+1 share sL rows p,p+1;
//      one thread emits both rows -> phase-2 iterations and LDS halved.
//      (clamped halo row makes the odd-row formula exact at oy=0)
//  Hot-loop form unchanged: division-derived per-iteration indices, c-outer
//  layers, 8x LDG.128 feats at loop top, duplicated weights in smem,
//  __launch_bounds__(128,4), TH=32.

#define WW    192
#define HH    128
#define HWSZ  (192*128)
#define CIN   8
#define TH    32
#define NROWS (TH + 1)           // 33 (+1 halo row above)
#define UPR   (WW/4)             // 48 four-pixel units per row
#define NUNIT (NROWS * UPR)      // 1584
#define OWW   384
#define OHH   256
#define NP    169

__device__ __forceinline__ float2 ffma2(float2 a, float2 b, float2 c) {
    float2 d;
    asm("fma.rn.f32x2 %0, %1, %2, %3;"
        : "=l"(reinterpret_cast<unsigned long long&>(d))
        : "l"(reinterpret_cast<unsigned long long&>(a)),
          "l"(reinterpret_cast<unsigned long long&>(b)),
          "l"(reinterpret_cast<unsigned long long&>(c)));
    return d;
}
__device__ __forceinline__ float2 relu2(float2 v) {
    return make_float2(fmaxf(v.x, 0.f), fmaxf(v.y, 0.f));
}
__device__ __forceinline__ float2 f2(float a, float b) { return make_float2(a, b); }

__global__ __launch_bounds__(128, 4) void dyn_mask_head_kernel(
    const float* __restrict__ mask_feats,   // [2, 8, 128, 192]
    const float* __restrict__ params,       // [n_inst, 169]
    const float* __restrict__ locs,         // [n_inst, 2] (x, y)
    const float* __restrict__ soi,          // [5]
    const int*   __restrict__ im_inds,      // [n_inst]
    const int*   __restrict__ fpn_levels,   // [n_inst]
    float*       __restrict__ out)          // [n_inst, 1, 256, 384]
{
    const int n   = blockIdx.y;
    const int r0  = blockIdx.x * TH;
    const int tid = threadIdx.x;

    __shared__ __align__(16) float sw1[8][20]; // w0..w7 dup(16) + bias dup(2) + pad
    __shared__ __align__(16) float sw2[20];    // w dup(16) + bias dup(2) + pad
    __shared__ __align__(16) float sL[NROWS][WW];
    __shared__ __align__(16) float sw0[8][24]; // w0..w9 dup(20) + bias dup(2) + pad

    {
        const float* p = params + n * NP;
        for (int t = tid; t < NP; t += 128) {
            float v = __ldg(p + t);
            if (t < 80) {
                int c = t / 10, j = t - 10 * c;
                sw0[c][2*j] = v; sw0[c][2*j+1] = v;
            } else if (t < 144) {
                int q = t - 80; int c = q >> 3, j = q & 7;
                sw1[c][2*j] = v; sw1[c][2*j+1] = v;
            } else if (t < 152) {
                int j = t - 144;
                sw2[2*j] = v; sw2[2*j+1] = v;
            } else if (t < 160) {
                int c = t - 152;
                sw0[c][20] = v; sw0[c][21] = v;
            } else if (t < 168) {
                int c = t - 160;
                sw1[c][16] = v; sw1[c][17] = v;
            } else {
                sw2[16] = v; sw2[17] = v;
            }
        }
    }
    __syncthreads();

    const int   im  = im_inds[n];
    const float inv = 1.0f / soi[fpn_levels[n]];
    const float lx  = locs[2*n + 0];
    const float ly  = locs[2*n + 1];
    const float* fb = mask_feats + (size_t)im * (CIN * HWSZ);
    const float s8  = 8.0f * inv;

    // ---- phase 1: logits, 4 consecutive pixels per thread per iter ----
#pragma unroll 1
    for (int it = 0; it < 13; it++) {
        const int i = tid + it * 128;
        if (i >= NUNIT) break;
        const int rl = i / UPR;
        const int m  = i - rl * UPR;
        const int x0 = 4 * m;
        const int rc = max(r0 - 1 + rl, 0);

        const float* fp = fb + rc * WW + x0;
        float4 f[8];
#pragma unroll
        for (int k = 0; k < 8; k++)
            f[k] = *reinterpret_cast<const float4*>(fp + k * HWSZ);

        const float ryv = (ly - (float)(rc * 8 + 4)) * inv;
        const float2 ryd = f2(ryv, ryv);
        const float rxv = (lx - (float)(x0 * 8 + 4)) * inv;
        const float2 rxA = f2(rxv, rxv - s8);
        const float2 rxB = f2(rxv - 2.f * s8, rxv - 3.f * s8);

        // ---- layer 0: 10 -> 8, relu. c-outer; ry-term folded into bias ----
        float2 hA[8], hB[8];
#pragma unroll
        for (int c = 0; c < 8; c++) {
            const float4* wc = reinterpret_cast<const float4*>(sw0[c]);
            const float2 bd = *reinterpret_cast<const float2*>(&sw0[c][20]);
            float4 w01 = wc[0];
            const float2 t0 = ffma2(f2(w01.z, w01.w), ryd, bd);  // shared A/B
            float2 aA = ffma2(f2(w01.x, w01.y), rxA, t0);
            float2 aB = ffma2(f2(w01.x, w01.y), rxB, t0);
#pragma unroll
            for (int kk = 0; kk < 4; kk++) {     // feats k = 2kk, 2kk+1
                float4 wp = wc[1 + kk];
                aA = ffma2(f2(wp.x, wp.y), f2(f[2*kk].x,   f[2*kk].y),   aA);
                aB = ffma2(f2(wp.x, wp.y), f2(f[2*kk].z,   f[2*kk].w),   aB);
                aA = ffma2(f2(wp.z, wp.w), f2(f[2*kk+1].x, f[2*kk+1].y), aA);
                aB = ffma2(f2(wp.z, wp.w), f2(f[2*kk+1].z, f[2*kk+1].w), aB);
            }
            hA[c] = relu2(aA);
            hB[c] = relu2(aB);
        }

        // ---- layer 1: 8 -> 8, relu ----
        float2 gA[8], gB[8];
#pragma unroll
        for (int c = 0; c < 8; c++) {
            const float4* wc = reinterpret_cast<const float4*>(sw1[c]);
            const float2 bd = *reinterpret_cast<const float2*>(&sw1[c][16]);
            float2 aA = bd, aB = bd;
#pragma unroll
            for (int kk = 0; kk < 4; kk++) {
                float4 wp = wc[kk];
                aA = ffma2(f2(wp.x, wp.y), hA[2*kk],   aA);
                aB = ffma2(f2(wp.x, wp.y), hB[2*kk],   aB);
                aA = ffma2(f2(wp.z, wp.w), hA[2*kk+1], aA);
                aB = ffma2(f2(wp.z, wp.w), hB[2*kk+1], aB);
            }
            gA[c] = relu2(aA);
            gB[c] = relu2(aB);
        }

        // ---- layer 2: 8 -> 1 ----
        {
            const float4* wc = reinterpret_cast<const float4*>(sw2);
            const float2 bd = *reinterpret_cast<const float2*>(&sw2[16]);
            float2 oA = bd, oB = bd;
#pragma unroll
            for (int kk = 0; kk < 4; kk++) {
                float4 wp = wc[kk];
                oA = ffma2(f2(wp.x, wp.y), gA[2*kk],   oA);
                oB = ffma2(f2(wp.x, wp.y), gB[2*kk],   oB);
                oA = ffma2(f2(wp.z, wp.w), gA[2*kk+1], oA);
                oB = ffma2(f2(wp.z, wp.w), gB[2*kk+1], oB);
            }
            float4 v = make_float4(oA.x, oA.y, oB.x, oB.y);
            *reinterpret_cast<float4*>(&sL[rl][x0]) = v;
        }
    }
    __syncthreads();

    // ---- phase 2: aligned_bilinear x2, ROW-PAIRED, 8 cols x 2 rows/thread ----
    // Output rows 2p and 2p+1 (local) both derive from sL[p], sL[p+1]:
    //   row 2p   = colinterp( 0.5*(sL[p] + sL[p+1]) )   [odd iy; exact at oy=0
    //              too because the clamped halo gives sL[0]==sL[1] there]
    //   row 2p+1 = colinterp( sL[p+1] )                 [even iy]
    float* ob = out + (size_t)n * (OHH * OWW) + (size_t)(2 * r0) * OWW;
    const int NG = TH * (OWW / 8);   // 32 row-pairs x 48 col-groups = 1536
#pragma unroll 1
    for (int it = 0; it < 12; it++) {
        const int g = tid + it * 128;
        if (g >= NG) break;
        const int p  = g / 48;
        const int q  = g - p * 48;
        const int c0 = 4 * q;

        const float4 a4 = *reinterpret_cast<const float4*>(&sL[p][c0]);
        const float4 b4 = *reinterpret_cast<const float4*>(&sL[p + 1][c0]);
        const float am1 = (q > 0) ? sL[p][c0 - 1]     : a4.x;
        const float bm1 = (q > 0) ? sL[p + 1][c0 - 1] : b4.x;

        // mid row values (for output row 2p)
        float4 mid;
        mid.x = 0.5f * (a4.x + b4.x);
        mid.y = 0.5f * (a4.y + b4.y);
        mid.z = 0.5f * (a4.z + b4.z);
        mid.w = 0.5f * (a4.w + b4.w);
        const float midm1 = 0.5f * (am1 + bm1);

        // column interpolation: out col 8q+0 = 0.5*(v[-1]+v[0]), 8q+1 = v[0], ...
        float4 r1a, r1b;   // row 2p
        r1a.x = 0.5f * (midm1 + mid.x);
        r1a.y = mid.x;
        r1a.z = 0.5f * (mid.x + mid.y);
        r1a.w = mid.y;
        r1b.x = 0.5f * (mid.y + mid.z);
        r1b.y = mid.z;
        r1b.z = 0.5f * (mid.z + mid.w);
        r1b.w = mid.w;

        float4 r2a, r2b;   // row 2p+1
        r2a.x = 0.5f * (bm1 + b4.x);
        r2a.y = b4.x;
        r2a.z = 0.5f * (b4.x + b4.y);
        r2a.w = b4.y;
        r2b.x = 0.5f * (b4.y + b4.z);
        r2b.y = b4.z;
        r2b.z = 0.5f * (b4.z + b4.w);
        r2b.w = b4.w;

        float* po = ob + (2 * p) * OWW + 8 * q;
        *reinterpret_cast<float4*>(po)           = r1a;
        *reinterpret_cast<float4*>(po + 4)       = r1b;
        *reinterpret_cast<float4*>(po + OWW)     = r2a;
        *reinterpret_cast<float4*>(po + OWW + 4) = r2b;
    }
}

extern "C" void kernel_launch(void* const* d_in, const int* in_sizes, int n_in,
                              void* d_out, int out_size) {
    const float* mask_feats = (const float*)d_in[0];
    const float* params     = (const float*)d_in[1];
    const float* locs       = (const float*)d_in[2];
    const float* soi        = (const float*)d_in[3];
    const int*   im_inds    = (const int*)d_in[4];
    const int*   fpn_levels = (const int*)d_in[5];
    float*       out        = (float*)d_out;

    const int n_inst = in_sizes[4];          // 256
    dim3 grid(HH / TH, n_inst);               // (4, 256)
    dyn_mask_head_kernel<<<grid, 128>>>(mask_feats, params, locs, soi,
                                        im_inds, fpn_levels, out);
}

// round 17
// speedup vs baseline: 1.0270x; 1.0270x over previous
#include <cuda_runtime.h>

// DynamicMaskHead fused kernel, round 17:
//  = round-15 VERBATIM (59.2us: TH=32, division-indexed hot loop, phase-2
//    8-cols/thread single-row) + ONE isolated change from R16:
//    layer-0 ry-term folded into the bias once per channel (saves 8 FFMA2
//    per unit on the binding fma pipe, at the cost of serializing both lane
//    chains through one t0 dependency).
//  R16's phase-2 row-pairing is REVERTED (suspected cause of the 59.2->59.6
//  regression). This run isolates which component hurt.

#define WW    192
#define HH    128
#define HWSZ  (192*128)
#define CIN   8
#define TH    32
#define NROWS (TH + 1)           // 33 (+1 halo row above)
#define UPR   (WW/4)             // 48 four-pixel units per row
#define NUNIT (NROWS * UPR)      // 1584
#define OWW   384
#define OHH   256
#define NP    169

__device__ __forceinline__ float2 ffma2(float2 a, float2 b, float2 c) {
    float2 d;
    asm("fma.rn.f32x2 %0, %1, %2, %3;"
        : "=l"(reinterpret_cast<unsigned long long&>(d))
        : "l"(reinterpret_cast<unsigned long long&>(a)),
          "l"(reinterpret_cast<unsigned long long&>(b)),
          "l"(reinterpret_cast<unsigned long long&>(c)));
    return d;
}
__device__ __forceinline__ float2 relu2(float2 v) {
    return make_float2(fmaxf(v.x, 0.f), fmaxf(v.y, 0.f));
}
__device__ __forceinline__ float2 f2(float a, float b) { return make_float2(a, b); }

__global__ __launch_bounds__(128, 4) void dyn_mask_head_kernel(
    const float* __restrict__ mask_feats,   // [2, 8, 128, 192]
    const float* __restrict__ params,       // [n_inst, 169]
    const float* __restrict__ locs,         // [n_inst, 2] (x, y)
    const float* __restrict__ soi,          // [5]
    const int*   __restrict__ im_inds,      // [n_inst]
    const int*   __restrict__ fpn_levels,   // [n_inst]
    float*       __restrict__ out)          // [n_inst, 1, 256, 384]
{
    const int n   = blockIdx.y;
    const int r0  = blockIdx.x * TH;
    const int tid = threadIdx.x;

    __shared__ __align__(16) float sw1[8][20]; // w0..w7 dup(16) + bias dup(2) + pad
    __shared__ __align__(16) float sw2[20];    // w dup(16) + bias dup(2) + pad
    __shared__ __align__(16) float sL[NROWS][WW];
    __shared__ __align__(16) float sw0[8][24]; // w0..w9 dup(20) + bias dup(2) + pad

    {
        const float* p = params + n * NP;
        for (int t = tid; t < NP; t += 128) {
            float v = __ldg(p + t);
            if (t < 80) {
                int c = t / 10, j = t - 10 * c;
                sw0[c][2*j] = v; sw0[c][2*j+1] = v;
            } else if (t < 144) {
                int q = t - 80; int c = q >> 3, j = q & 7;
                sw1[c][2*j] = v; sw1[c][2*j+1] = v;
            } else if (t < 152) {
                int j = t - 144;
                sw2[2*j] = v; sw2[2*j+1] = v;
            } else if (t < 160) {
                int c = t - 152;
                sw0[c][20] = v; sw0[c][21] = v;
            } else if (t < 168) {
                int c = t - 160;
                sw1[c][16] = v; sw1[c][17] = v;
            } else {
                sw2[16] = v; sw2[17] = v;
            }
        }
    }
    __syncthreads();

    const int   im  = im_inds[n];
    const float inv = 1.0f / soi[fpn_levels[n]];
    const float lx  = locs[2*n + 0];
    const float ly  = locs[2*n + 1];
    const float* fb = mask_feats + (size_t)im * (CIN * HWSZ);
    const float s8  = 8.0f * inv;

    // ---- phase 1: logits, 4 consecutive pixels per thread per iter ----
#pragma unroll 1
    for (int it = 0; it < 13; it++) {
        const int i = tid + it * 128;
        if (i >= NUNIT) break;
        const int rl = i / UPR;
        const int m  = i - rl * UPR;
        const int x0 = 4 * m;
        const int rc = max(r0 - 1 + rl, 0);

        const float* fp = fb + rc * WW + x0;
        float4 f[8];
#pragma unroll
        for (int k = 0; k < 8; k++)
            f[k] = *reinterpret_cast<const float4*>(fp + k * HWSZ);

        const float ryv = (ly - (float)(rc * 8 + 4)) * inv;
        const float2 ryd = f2(ryv, ryv);
        const float rxv = (lx - (float)(x0 * 8 + 4)) * inv;
        const float2 rxA = f2(rxv, rxv - s8);
        const float2 rxB = f2(rxv - 2.f * s8, rxv - 3.f * s8);

        // ---- layer 0: 10 -> 8, relu. c-outer; ry-term folded into bias ----
        float2 hA[8], hB[8];
#pragma unroll
        for (int c = 0; c < 8; c++) {
            const float4* wc = reinterpret_cast<const float4*>(sw0[c]);
            const float2 bd = *reinterpret_cast<const float2*>(&sw0[c][20]);
            float4 w01 = wc[0];
            const float2 t0 = ffma2(f2(w01.z, w01.w), ryd, bd);  // shared A/B
            float2 aA = ffma2(f2(w01.x, w01.y), rxA, t0);
            float2 aB = ffma2(f2(w01.x, w01.y), rxB, t0);
#pragma unroll
            for (int kk = 0; kk < 4; kk++) {     // feats k = 2kk, 2kk+1
                float4 wp = wc[1 + kk];
                aA = ffma2(f2(wp.x, wp.y), f2(f[2*kk].x,   f[2*kk].y),   aA);
                aB = ffma2(f2(wp.x, wp.y), f2(f[2*kk].z,   f[2*kk].w),   aB);
                aA = ffma2(f2(wp.z, wp.w), f2(f[2*kk+1].x, f[2*kk+1].y), aA);
                aB = ffma2(f2(wp.z, wp.w), f2(f[2*kk+1].z, f[2*kk+1].w), aB);
            }
            hA[c] = relu2(aA);
            hB[c] = relu2(aB);
        }

        // ---- layer 1: 8 -> 8, relu ----
        float2 gA[8], gB[8];
#pragma unroll
        for (int c = 0; c < 8; c++) {
            const float4* wc = reinterpret_cast<const float4*>(sw1[c]);
            const float2 bd = *reinterpret_cast<const float2*>(&sw1[c][16]);
            float2 aA = bd, aB = bd;
#pragma unroll
            for (int kk = 0; kk < 4; kk++) {
                float4 wp = wc[kk];
                aA = ffma2(f2(wp.x, wp.y), hA[2*kk],   aA);
                aB = ffma2(f2(wp.x, wp.y), hB[2*kk],   aB);
                aA = ffma2(f2(wp.z, wp.w), hA[2*kk+1], aA);
                aB = ffma2(f2(wp.z, wp.w), hB[2*kk+1], aB);
            }
            gA[c] = relu2(aA);
            gB[c] = relu2(aB);
        }

        // ---- layer 2: 8 -> 1 ----
        {
            const float4* wc = reinterpret_cast<const float4*>(sw2);
            const float2 bd = *reinterpret_cast<const float2*>(&sw2[16]);
            float2 oA = bd, oB = bd;
#pragma unroll
            for (int kk = 0; kk < 4; kk++) {
                float4 wp = wc[kk];
                oA = ffma2(f2(wp.x, wp.y), gA[2*kk],   oA);
                oB = ffma2(f2(wp.x, wp.y), gB[2*kk],   oB);
                oA = ffma2(f2(wp.z, wp.w), gA[2*kk+1], oA);
                oB = ffma2(f2(wp.z, wp.w), gB[2*kk+1], oB);
            }
            float4 v = make_float4(oA.x, oA.y, oB.x, oB.y);
            *reinterpret_cast<float4*>(&sL[rl][x0]) = v;
        }
    }
    __syncthreads();

    // ---- phase 2: aligned_bilinear x2, 8 output cols per thread per iter ----
    // (R15 form, reverted from R16's row pairing)
    // out[o] = interp[max(o-1,0)]; interp[j] even -> t[j/2],
    //                               odd  -> 0.5*(t[j>>1] + t[(j>>1)+1])
    float* ob = out + (size_t)n * (OHH * OWW) + (size_t)(2 * r0) * OWW;
    const int NG = (2 * TH) * (OWW / 8);   // 64 rows x 48 groups = 3072
    for (int g = tid; g < NG; g += 128) {
        const int oyl = g / 48;
        const int q   = g - oyl * 48;
        const int oy  = 2 * r0 + oyl;
        const int iy  = max(oy - 1, 0);
        const int ra  = (iy >> 1) - r0 + 1;   // smem slot of row (iy>>1)
        const int c0  = 4 * q;

        float4 v; float vm1;
        if (iy & 1) {
            const float4 a = *reinterpret_cast<const float4*>(&sL[ra][c0]);
            const float4 b = *reinterpret_cast<const float4*>(&sL[ra + 1][c0]);
            v.x = 0.5f * (a.x + b.x);
            v.y = 0.5f * (a.y + b.y);
            v.z = 0.5f * (a.z + b.z);
            v.w = 0.5f * (a.w + b.w);
            vm1 = (q > 0) ? 0.5f * (sL[ra][c0 - 1] + sL[ra + 1][c0 - 1]) : v.x;
        } else {
            v   = *reinterpret_cast<const float4*>(&sL[ra][c0]);
            vm1 = (q > 0) ? sL[ra][c0 - 1] : v.x;
        }

        float4 o1, o2;
        o1.x = 0.5f * (vm1 + v.x);   // out col 8q   (q==0: vm1=v.x -> v.x)
        o1.y = v.x;                  // 8q+1
        o1.z = 0.5f * (v.x + v.y);   // 8q+2
        o1.w = v.y;                  // 8q+3
        o2.x = 0.5f * (v.y + v.z);   // 8q+4
        o2.y = v.z;                  // 8q+5
        o2.z = 0.5f * (v.z + v.w);   // 8q+6
        o2.w = v.w;                  // 8q+7
        float* po = ob + oyl * OWW + 8 * q;
        *reinterpret_cast<float4*>(po)     = o1;
        *reinterpret_cast<float4*>(po + 4) = o2;
    }
}

extern "C" void kernel_launch(void* const* d_in, const int* in_sizes, int n_in,
                              void* d_out, int out_size) {
    const float* mask_feats = (const float*)d_in[0];
    const float* params     = (const float*)d_in[1];
    const float* locs       = (const float*)d_in[2];
    const float* soi        = (const float*)d_in[3];
    const int*   im_inds    = (const int*)d_in[4];
    const int*   fpn_levels = (const int*)d_in[5];
    float*       out        = (float*)d_out;

    const int n_inst = in_sizes[4];          // 256
    dim3 grid(HH / TH, n_inst);               // (4, 256)
    dyn_mask_head_kernel<<<grid, 128>>>(mask_feats, params, locs, soi,
                                        im_inds, fpn_levels, out);
}